// round 15
// baseline (speedup 1.0000x reference)
#include <cuda_runtime.h>

#define H     64
#define NPB   128          // nodes per tile
#define NT    256
#define MAXN  100000
#define MAXE  1000000
#define SROW  128          // activation row stride (floats)
#define NTILES ((MAXN + NPB - 1) / NPB)
#define PGRID  444         // persistent node grid (3 per SM)

// Scratch (allocation-free rule). g_agg is pre-seeded with x each conv,
// so edge REDs accumulate on top of x. Replay-safe: init rewrites both.
__device__ float g_x[MAXN * H];
__device__ float g_agg[MAXN * H];
__device__ int   g_ctr[3];           // node work-stealing counters
__device__ int   g_deg[MAXN];        // src-sort build: per-src degree
__device__ int   g_off[MAXN + 1];
__device__ int   g_cur[MAXN];
__device__ int   g_eid[MAXE];        // edge ids sorted by src
__device__ int   g_srcs[MAXE];       // src ids sorted (locality stream)
__device__ int   g_dsts[MAXE];       // dst ids sorted by src

__device__ __forceinline__ int rotn(int k, int n) {
    return (n + ((k >> 2) << 3) + ((k >> 4) << 2)) & 127;
}

// ---------------- src-sort build (per replay; edge_index constant) -----------

__global__ __launch_bounds__(256) void zero_deg_kernel(int n) {
    int t = blockIdx.x * 256 + threadIdx.x;
    if (t < n) g_deg[t] = 0;
}

__global__ __launch_bounds__(256) void count_kernel(const int* __restrict__ key, int E) {
    int e = blockIdx.x * 256 + threadIdx.x;
    if (e < E) atomicAdd(&g_deg[__ldg(key + e)], 1);
}

__global__ __launch_bounds__(1024) void scan_kernel(int n) {
    __shared__ int sc[1024];
    int tid = threadIdx.x;
    int per = (n + 1023) / 1024;
    int base = tid * per;
    int sum = 0;
    for (int i = 0; i < per; ++i) {
        int idx = base + i;
        if (idx < n) sum += g_deg[idx];
    }
    sc[tid] = sum;
    __syncthreads();
    for (int ofs = 1; ofs < 1024; ofs <<= 1) {
        int v = (tid >= ofs) ? sc[tid - ofs] : 0;
        __syncthreads();
        sc[tid] += v;
        __syncthreads();
    }
    int run = sc[tid] - sum;
    for (int i = 0; i < per; ++i) {
        int idx = base + i;
        if (idx < n) {
            g_off[idx] = run;
            g_cur[idx] = run;
            run += g_deg[idx];
        }
    }
    if (tid == 1023) g_off[n] = sc[1023];
}

__global__ __launch_bounds__(256) void fill_kernel(const int* __restrict__ src,
                                                   const int* __restrict__ dst, int E) {
    int e = blockIdx.x * 256 + threadIdx.x;
    if (e < E) {
        int s = __ldg(src + e);
        int slot = atomicAdd(&g_cur[s], 1);
        g_eid[slot]  = e;
        g_srcs[slot] = s;
        g_dsts[slot] = __ldg(dst + e);
    }
}

// ---------------- x = node_emb[z] -> g_x AND g_agg ----------------
__global__ __launch_bounds__(256) void init_kernel(const float* __restrict__ node_emb,
                                                   const int* __restrict__ z,
                                                   int lo, int hi) {
    int t = blockIdx.x * 256 + threadIdx.x;
    int total = (hi - lo) * (H / 4);
    if (t >= total) return;
    int node = lo + (t >> 4);
    int p    = t & 15;
    int zi   = __ldg(z + node);
    float4 v = ((const float4*)node_emb)[zi * 16 + p];
    ((float4*)g_x)[(size_t)node * 16 + p]   = v;
    ((float4*)g_agg)[(size_t)node * 16 + p] = v;
}

// msg = relu(x[src] + edge_attr); vector-RED scatter into g_agg[dst].
// Edges processed in SRC-SORTED order: x[src] rows get ~deg consecutive
// reuses on the same SM -> L1 hits instead of L2 traffic. ea reads stay
// 256B-row coalesced (16 lanes per edge); 2 adjacent sorted edges/thread.
__global__ __launch_bounds__(256) void edge_kernel(const float* __restrict__ ea,
                                                   int E) {
    int t = blockIdx.x * 256 + threadIdx.x;
    int grp = t >> 4;                 // 16-lane group -> 2 consecutive edges
    int p   = t & 15;
    int i1 = 2 * grp, i2 = i1 + 1;
    if (i2 >= E) {
        if (i1 >= E) return;
        int e = __ldg(g_eid + i1), s = __ldg(g_srcs + i1), d = __ldg(g_dsts + i1);
        float4 a  = __ldcs((const float4*)ea + (size_t)e * 16 + p);
        float4 xv = ((const float4*)g_x)[(size_t)s * 16 + p];
        float4 m = make_float4(fmaxf(a.x + xv.x, 0.f), fmaxf(a.y + xv.y, 0.f),
                               fmaxf(a.z + xv.z, 0.f), fmaxf(a.w + xv.w, 0.f));
        float* o = g_agg + ((size_t)d << 6) + (p << 2);
        asm volatile("red.global.add.v4.f32 [%0], {%1, %2, %3, %4};"
                     :: "l"(o), "f"(m.x), "f"(m.y), "f"(m.z), "f"(m.w) : "memory");
        return;
    }

    int e1 = __ldg(g_eid + i1),  e2 = __ldg(g_eid + i2);
    int s1 = __ldg(g_srcs + i1), s2 = __ldg(g_srcs + i2);
    int d1 = __ldg(g_dsts + i1), d2 = __ldg(g_dsts + i2);

    float4 a1 = __ldcs((const float4*)ea + (size_t)e1 * 16 + p);
    float4 a2 = __ldcs((const float4*)ea + (size_t)e2 * 16 + p);
    float4 x1 = ((const float4*)g_x)[(size_t)s1 * 16 + p];
    float4 x2 = ((const float4*)g_x)[(size_t)s2 * 16 + p];   // usually L1 hit

    float4 m1 = make_float4(fmaxf(a1.x + x1.x, 0.f), fmaxf(a1.y + x1.y, 0.f),
                            fmaxf(a1.z + x1.z, 0.f), fmaxf(a1.w + x1.w, 0.f));
    float4 m2 = make_float4(fmaxf(a2.x + x2.x, 0.f), fmaxf(a2.y + x2.y, 0.f),
                            fmaxf(a2.z + x2.z, 0.f), fmaxf(a2.w + x2.w, 0.f));

    float* o1 = g_agg + ((size_t)d1 << 6) + (p << 2);
    float* o2 = g_agg + ((size_t)d2 << 6) + (p << 2);
    asm volatile("red.global.add.v4.f32 [%0], {%1, %2, %3, %4};"
                 :: "l"(o1), "f"(m1.x), "f"(m1.y), "f"(m1.z), "f"(m1.w) : "memory");
    asm volatile("red.global.add.v4.f32 [%0], {%1, %2, %3, %4};"
                 :: "l"(o2), "f"(m2.x), "f"(m2.y), "f"(m2.z), "f"(m2.w) : "memory");
}

// ---------------- persistent node MLP (R14 form, unchanged) -----------------
__global__ __launch_bounds__(NT, 3) void node_kernel(const float* __restrict__ W1g,
                                                     const float* __restrict__ b1g,
                                                     const float* __restrict__ W2g,
                                                     const float* __restrict__ b2g,
                                                     int n, int relu_out,
                                                     float* __restrict__ dout, int last,
                                                     int conv) {
    extern __shared__ float sm[];
    float* sW1 = sm;
    float* sW2 = sm + 4096;
    float* sA  = sm + 8192;
    float* sb1 = sm + 8192 + H * SROW;
    float* sb2 = sb1 + H;
    __shared__ int s_tile;

    int tid = threadIdx.x;

    if (blockIdx.x == 0 && tid == 0) g_ctr[(conv + 1) % 3] = 0;

    for (int idx = tid; idx < H * H; idx += NT) {
        int j = idx >> 6, k = idx & 63;
        sW1[k * H + j] = W1g[idx];
        sW2[k * H + j] = W2g[idx];
    }
    if (tid < H) { sb1[tid] = b1g[tid]; sb2[tid] = b2g[tid]; }

    int jIdx = tid & 15;
    int nIdx = tid >> 4;
    int j0 = jIdx * 4;
    int n0 = nIdx * 8;

    if (tid == 0) s_tile = atomicAdd(&g_ctr[conv], 1);
    __syncthreads();

    float4 b1v = *(const float4*)(sb1 + j0);
    float4 b2v = *(const float4*)(sb2 + j0);
    float* xout = last ? dout : g_x;

    for (;;) {
        int tile = s_tile;
        if (tile >= NTILES) break;
        int base = tile * NPB;

        #pragma unroll
        for (int it = 0; it < 8; ++it) {
            int idx = tid + it * NT;
            int row = idx >> 4, c = (idx & 15) << 2, g = base + row;
            float4 v = make_float4(0.f, 0.f, 0.f, 0.f);
            if (g < n)
                v = *(const float4*)(g_agg + (size_t)g * H + c);
            sA[(c + 0) * SROW + rotn(c + 0, row)] = v.x;
            sA[(c + 1) * SROW + rotn(c + 1, row)] = v.y;
            sA[(c + 2) * SROW + rotn(c + 2, row)] = v.z;
            sA[(c + 3) * SROW + rotn(c + 3, row)] = v.w;
        }
        __syncthreads();

        float acc[8][4];

        #pragma unroll
        for (int q = 0; q < 8; ++q)
            #pragma unroll
            for (int jj = 0; jj < 4; ++jj) acc[q][jj] = 0.f;

        #pragma unroll 8
        for (int k = 0; k < H; ++k) {
            const float* rowp = sA + k * SROW;
            float4 aA = *(const float4*)(rowp + rotn(k, n0));
            float4 aB = *(const float4*)(rowp + rotn(k, n0 + 4));
            float4 w  = *(const float4*)(sW1 + k * H + j0);
            float av_[8] = {aA.x, aA.y, aA.z, aA.w, aB.x, aB.y, aB.z, aB.w};
            float wv_[4] = {w.x, w.y, w.z, w.w};
            #pragma unroll
            for (int q = 0; q < 8; ++q)
                #pragma unroll
                for (int jj = 0; jj < 4; ++jj)
                    acc[q][jj] = fmaf(av_[q], wv_[jj], acc[q][jj]);
        }
        __syncthreads();

        #pragma unroll
        for (int jj = 0; jj < 4; ++jj) {
            float b = (jj == 0) ? b1v.x : (jj == 1) ? b1v.y : (jj == 2) ? b1v.z : b1v.w;
            int kr = j0 + jj;
            float* rowp = sA + kr * SROW;
            #pragma unroll
            for (int p = 0; p < 4; ++p) {
                float2 hv = make_float2(fmaxf(acc[2 * p][jj] + b, 0.f),
                                        fmaxf(acc[2 * p + 1][jj] + b, 0.f));
                *(float2*)(rowp + rotn(kr, n0 + 2 * p)) = hv;
            }
        }
        __syncthreads();

        #pragma unroll
        for (int q = 0; q < 8; ++q)
            #pragma unroll
            for (int jj = 0; jj < 4; ++jj) acc[q][jj] = 0.f;

        #pragma unroll 8
        for (int k = 0; k < H; ++k) {
            const float* rowp = sA + k * SROW;
            float4 aA = *(const float4*)(rowp + rotn(k, n0));
            float4 aB = *(const float4*)(rowp + rotn(k, n0 + 4));
            float4 w  = *(const float4*)(sW2 + k * H + j0);
            float av_[8] = {aA.x, aA.y, aA.z, aA.w, aB.x, aB.y, aB.z, aB.w};
            float wv_[4] = {w.x, w.y, w.z, w.w};
            #pragma unroll
            for (int q = 0; q < 8; ++q)
                #pragma unroll
                for (int jj = 0; jj < 4; ++jj)
                    acc[q][jj] = fmaf(av_[q], wv_[jj], acc[q][jj]);
        }

        if (tid == 0) s_tile = atomicAdd(&g_ctr[conv], 1);

        #pragma unroll
        for (int q = 0; q < 8; ++q) {
            int g = base + n0 + q;
            if (g < n) {
                float4 o = make_float4(acc[q][0] + b2v.x, acc[q][1] + b2v.y,
                                       acc[q][2] + b2v.z, acc[q][3] + b2v.w);
                if (relu_out) {
                    o.x = fmaxf(o.x, 0.f); o.y = fmaxf(o.y, 0.f);
                    o.z = fmaxf(o.z, 0.f); o.w = fmaxf(o.w, 0.f);
                }
                size_t off = (size_t)g * H + j0;
                float4 r = *(const float4*)(g_x + off);
                o.x += r.x; o.y += r.y; o.z += r.z; o.w += r.w;
                *(float4*)(xout + off) = o;
                if (!last)
                    *(float4*)(g_agg + off) = o;   // seed next conv
            }
        }
        __syncthreads();
    }
}

static const int NODE_SMEM_BYTES = (8192 + H * SROW + 2 * H) * (int)sizeof(float);

extern "C" void kernel_launch(void* const* d_in, const int* in_sizes, int n_in,
                              void* d_out, int out_size) {
    const float* node_emb  = (const float*)d_in[0];
    const float* W1        = (const float*)d_in[1];
    const float* b1        = (const float*)d_in[2];
    const float* W2        = (const float*)d_in[3];
    const float* b2        = (const float*)d_in[4];
    const float* edge_attr = (const float*)d_in[5];
    const int*   z         = (const int*)d_in[6];
    const int*   eidx      = (const int*)d_in[7];

    int n = in_sizes[6];        // 100000 nodes
    int E = in_sizes[7] / 2;    // 1000000 edges
    float* out = (float*)d_out;
    const int* src = eidx;
    const int* dst = eidx + E;

    cudaFuncSetAttribute(node_kernel, cudaFuncAttributeMaxDynamicSharedMemorySize,
                         NODE_SMEM_BYTES);

    // src-sort build (edge_index constant; rebuilt every replay)
    zero_deg_kernel<<<(n + 255) / 256, 256>>>(n);
    count_kernel<<<(E + 255) / 256, 256>>>(src, E);
    scan_kernel<<<1, 1024>>>(n);
    fill_kernel<<<(E + 255) / 256, 256>>>(src, dst, E);

    int nh = n / 2;
    init_kernel<<<(nh * (H / 4) + 255) / 256, 256>>>(node_emb, z, 0, nh);
    init_kernel<<<((n - nh) * (H / 4) + 255) / 256, 256>>>(node_emb, z, nh, n);

    int edge_blocks = ((E / 2) * 16 + 255) / 256;

    for (int i = 0; i < 3; ++i) {
        edge_kernel<<<edge_blocks, 256>>>(edge_attr, E);
        node_kernel<<<PGRID, NT, NODE_SMEM_BYTES>>>(
            W1 + i * H * H, b1 + i * H, W2 + i * H * H, b2 + i * H,
            n, /*relu_out=*/(i < 2) ? 1 : 0, out, /*last=*/(i == 2) ? 1 : 0, i);
    }
}

// round 16
// speedup vs baseline: 1.5319x; 1.5319x over previous
#include <cuda_runtime.h>

#define H     64
#define NPB   128          // nodes per tile
#define NT    256
#define MAXN  100000
#define SROW  128          // activation row stride (floats)
#define NTILES ((MAXN + NPB - 1) / NPB)
#define PGRID  444         // persistent node grid (3 per SM)

// Scratch (allocation-free rule). g_agg is pre-seeded with x each conv
// (init / node epilogue dual-store), so edge REDs accumulate on top of x
// and g_agg is directly the MLP input. Replay-safe: init rewrites both.
__device__ float g_x[MAXN * H];
__device__ float g_agg[MAXN * H];
__device__ int   g_ctr[3];           // node work-stealing counters

// Column rotation: spreads banks for transposed STS while keeping per-k GEMM
// reads broadcast and 16B-aligned. Constant over groups of 4 consecutive k.
__device__ __forceinline__ int rotn(int k, int n) {
    return (n + ((k >> 2) << 3) + ((k >> 4) << 2)) & 127;
}

// x = node_emb[z] -> g_x AND g_agg. Split in two so ncu -s 5 lands on node.
__global__ __launch_bounds__(256) void init_kernel(const float* __restrict__ node_emb,
                                                   const int* __restrict__ z,
                                                   int lo, int hi) {
    int t = blockIdx.x * 256 + threadIdx.x;
    int total = (hi - lo) * (H / 4);
    if (t >= total) return;
    int node = lo + (t >> 4);
    int p    = t & 15;
    int zi   = __ldg(z + node);
    float4 v = ((const float4*)node_emb)[zi * 16 + p];
    ((float4*)g_x)[(size_t)node * 16 + p]   = v;
    ((float4*)g_agg)[(size_t)node * 16 + p] = v;
}

// msg = relu(x[src] + edge_attr); vector-RED scatter into g_agg[dst]
// (g_agg pre-seeded with x). 16 threads/edge; ADJACENT edge pair per thread
// (512B-contiguous ea reads per lane group, int2 index loads); loads batched.
__global__ __launch_bounds__(256) void edge_kernel(const float* __restrict__ ea,
                                                   const int* __restrict__ src,
                                                   const int* __restrict__ dst, int E) {
    int half = E >> 1;
    int t = blockIdx.x * 256 + threadIdx.x;
    if (t >= half * 16) return;
    int grp = t >> 4;                  // handles edges 2*grp, 2*grp+1
    int p   = t & 15;
    int e1  = 2 * grp;

    int2 ss = __ldg((const int2*)src + grp);   // s1, s2
    int2 dd = __ldg((const int2*)dst + grp);   // d1, d2

    const float4* pe = (const float4*)ea + (size_t)e1 * 16 + p;
    float4 a1 = __ldcs(pe);
    float4 a2 = __ldcs(pe + 16);
    float4 x1 = ((const float4*)g_x)[(size_t)ss.x * 16 + p];
    float4 x2 = ((const float4*)g_x)[(size_t)ss.y * 16 + p];

    float4 m1 = make_float4(fmaxf(a1.x + x1.x, 0.f), fmaxf(a1.y + x1.y, 0.f),
                            fmaxf(a1.z + x1.z, 0.f), fmaxf(a1.w + x1.w, 0.f));
    float4 m2 = make_float4(fmaxf(a2.x + x2.x, 0.f), fmaxf(a2.y + x2.y, 0.f),
                            fmaxf(a2.z + x2.z, 0.f), fmaxf(a2.w + x2.w, 0.f));

    float* o1 = g_agg + ((size_t)dd.x << 6) + (p << 2);
    float* o2 = g_agg + ((size_t)dd.y << 6) + (p << 2);
    asm volatile("red.global.add.v4.f32 [%0], {%1, %2, %3, %4};"
                 :: "l"(o1), "f"(m1.x), "f"(m1.y), "f"(m1.z), "f"(m1.w) : "memory");
    asm volatile("red.global.add.v4.f32 [%0], {%1, %2, %3, %4};"
                 :: "l"(o2), "f"(m2.x), "f"(m2.y), "f"(m2.z), "f"(m2.w) : "memory");
}

// Persistent node MLP with dynamic tile stealing (R14 structure).
// GEMM loops kk-grouped: rotation hoisted (constant per 4 k), inner
// addressing is pure pointer increments -> more issue slots for FFMA.
__global__ __launch_bounds__(NT, 3) void node_kernel(const float* __restrict__ W1g,
                                                     const float* __restrict__ b1g,
                                                     const float* __restrict__ W2g,
                                                     const float* __restrict__ b2g,
                                                     int n, int relu_out,
                                                     float* __restrict__ dout, int last,
                                                     int conv) {
    extern __shared__ float sm[];
    float* sW1 = sm;                         // 4096
    float* sW2 = sm + 4096;                  // 4096
    float* sA  = sm + 8192;                  // 64 x 128 rotated
    float* sb1 = sm + 8192 + H * SROW;       // 64
    float* sb2 = sb1 + H;                    // 64
    __shared__ int s_tile;

    int tid = threadIdx.x;

    if (blockIdx.x == 0 && tid == 0) g_ctr[(conv + 1) % 3] = 0;

    for (int idx = tid; idx < H * H; idx += NT) {
        int j = idx >> 6, k = idx & 63;
        sW1[k * H + j] = W1g[idx];
        sW2[k * H + j] = W2g[idx];
    }
    if (tid < H) { sb1[tid] = b1g[tid]; sb2[tid] = b2g[tid]; }

    int jIdx = tid & 15;
    int nIdx = tid >> 4;
    int j0 = jIdx * 4;
    int n0 = nIdx * 8;

    if (tid == 0) s_tile = atomicAdd(&g_ctr[conv], 1);
    __syncthreads();

    float4 b1v = *(const float4*)(sb1 + j0);
    float4 b2v = *(const float4*)(sb2 + j0);
    float* xout = last ? dout : g_x;

    for (;;) {
        int tile = s_tile;
        if (tile >= NTILES) break;
        int base = tile * NPB;

        // ---- Prologue: load g_agg (= x + Σmsg), transpose+rotate into sA.
        #pragma unroll
        for (int it = 0; it < 8; ++it) {
            int idx = tid + it * NT;
            int row = idx >> 4, c = (idx & 15) << 2, g = base + row;
            float4 v = make_float4(0.f, 0.f, 0.f, 0.f);
            if (g < n)
                v = *(const float4*)(g_agg + (size_t)g * H + c);
            float* rowp = sA + c * SROW + rotn(c, row);  // rot const for c..c+3
            rowp[0]        = v.x;
            rowp[SROW]     = v.y;
            rowp[2 * SROW] = v.z;
            rowp[3 * SROW] = v.w;
        }
        __syncthreads();

        float acc[8][4];

        // ---- Layer 1: scalar FFMA GEMM, kk-grouped addressing ----
        #pragma unroll
        for (int q = 0; q < 8; ++q)
            #pragma unroll
            for (int jj = 0; jj < 4; ++jj) acc[q][jj] = 0.f;

        #pragma unroll 4
        for (int kk = 0; kk < H / 4; ++kk) {
            int kb = kk * 4;
            const float* pA = sA + kb * SROW + rotn(kb, n0);
            const float* pB = sA + kb * SROW + rotn(kb, n0 + 4);
            const float* pW = sW1 + kb * H + j0;
            #pragma unroll
            for (int dk = 0; dk < 4; ++dk) {
                float4 aA = *(const float4*)(pA + dk * SROW);
                float4 aB = *(const float4*)(pB + dk * SROW);
                float4 w  = *(const float4*)(pW + dk * H);
                float av_[8] = {aA.x, aA.y, aA.z, aA.w, aB.x, aB.y, aB.z, aB.w};
                float wv_[4] = {w.x, w.y, w.z, w.w};
                #pragma unroll
                for (int q = 0; q < 8; ++q)
                    #pragma unroll
                    for (int jj = 0; jj < 4; ++jj)
                        acc[q][jj] = fmaf(av_[q], wv_[jj], acc[q][jj]);
            }
        }
        __syncthreads();       // all reads of sA done

        // h1 = relu(acc + b1) -> sA (row = j role)
        #pragma unroll
        for (int jj = 0; jj < 4; ++jj) {
            float b = (jj == 0) ? b1v.x : (jj == 1) ? b1v.y : (jj == 2) ? b1v.z : b1v.w;
            int kr = j0 + jj;
            float* rowp = sA + kr * SROW;
            #pragma unroll
            for (int p = 0; p < 4; ++p) {
                float2 hv = make_float2(fmaxf(acc[2 * p][jj] + b, 0.f),
                                        fmaxf(acc[2 * p + 1][jj] + b, 0.f));
                *(float2*)(rowp + rotn(kr, n0 + 2 * p)) = hv;
            }
        }
        __syncthreads();

        // ---- Layer 2 ----
        #pragma unroll
        for (int q = 0; q < 8; ++q)
            #pragma unroll
            for (int jj = 0; jj < 4; ++jj) acc[q][jj] = 0.f;

        #pragma unroll 4
        for (int kk = 0; kk < H / 4; ++kk) {
            int kb = kk * 4;
            const float* pA = sA + kb * SROW + rotn(kb, n0);
            const float* pB = sA + kb * SROW + rotn(kb, n0 + 4);
            const float* pW = sW2 + kb * H + j0;
            #pragma unroll
            for (int dk = 0; dk < 4; ++dk) {
                float4 aA = *(const float4*)(pA + dk * SROW);
                float4 aB = *(const float4*)(pB + dk * SROW);
                float4 w  = *(const float4*)(pW + dk * H);
                float av_[8] = {aA.x, aA.y, aA.z, aA.w, aB.x, aB.y, aB.z, aB.w};
                float wv_[4] = {w.x, w.y, w.z, w.w};
                #pragma unroll
                for (int q = 0; q < 8; ++q)
                    #pragma unroll
                    for (int jj = 0; jj < 4; ++jj)
                        acc[q][jj] = fmaf(av_[q], wv_[jj], acc[q][jj]);
            }
        }

        // Steal next tile while epilogue drains.
        if (tid == 0) s_tile = atomicAdd(&g_ctr[conv], 1);

        // ---- Epilogue: +b2, optional relu, +residual; dual-store new x ----
        #pragma unroll
        for (int q = 0; q < 8; ++q) {
            int g = base + n0 + q;
            if (g < n) {
                float4 o = make_float4(acc[q][0] + b2v.x, acc[q][1] + b2v.y,
                                       acc[q][2] + b2v.z, acc[q][3] + b2v.w);
                if (relu_out) {
                    o.x = fmaxf(o.x, 0.f); o.y = fmaxf(o.y, 0.f);
                    o.z = fmaxf(o.z, 0.f); o.w = fmaxf(o.w, 0.f);
                }
                size_t off = (size_t)g * H + j0;
                float4 r = *(const float4*)(g_x + off);
                o.x += r.x; o.y += r.y; o.z += r.z; o.w += r.w;
                *(float4*)(xout + off) = o;
                if (!last)
                    *(float4*)(g_agg + off) = o;   // seed next conv
            }
        }
        __syncthreads();       // s_tile update / sA reuse ordered
    }
}

static const int NODE_SMEM_BYTES = (8192 + H * SROW + 2 * H) * (int)sizeof(float);

extern "C" void kernel_launch(void* const* d_in, const int* in_sizes, int n_in,
                              void* d_out, int out_size) {
    const float* node_emb  = (const float*)d_in[0];
    const float* W1        = (const float*)d_in[1];
    const float* b1        = (const float*)d_in[2];
    const float* W2        = (const float*)d_in[3];
    const float* b2        = (const float*)d_in[4];
    const float* edge_attr = (const float*)d_in[5];
    const int*   z         = (const int*)d_in[6];
    const int*   eidx      = (const int*)d_in[7];

    int n = in_sizes[6];        // 100000 nodes
    int E = in_sizes[7] / 2;    // 1000000 edges
    float* out = (float*)d_out;

    cudaFuncSetAttribute(node_kernel, cudaFuncAttributeMaxDynamicSharedMemorySize,
                         NODE_SMEM_BYTES);

    int nh = n / 2;
    init_kernel<<<(nh * (H / 4) + 255) / 256, 256>>>(node_emb, z, 0, nh);
    init_kernel<<<((n - nh) * (H / 4) + 255) / 256, 256>>>(node_emb, z, nh, n);

    int edge_blocks = ((E / 2) * 16 + 255) / 256;

    for (int i = 0; i < 3; ++i) {
        edge_kernel<<<edge_blocks, 256>>>(edge_attr, eidx, eidx + E, E);
        node_kernel<<<PGRID, NT, NODE_SMEM_BYTES>>>(
            W1 + i * H * H, b1 + i * H, W2 + i * H * H, b2 + i * H,
            n, /*relu_out=*/(i < 2) ? 1 : 0, out, /*last=*/(i == 2) ? 1 : 0, i);
    }
}